// round 8
// baseline (speedup 1.0000x reference)
#include <cuda_runtime.h>
#include <cuda_bf16.h>
#include <cstdio>

// ============================================================================
// CfC Liquid Neural Network, B=256, T=1024.
//  - Pack phase: mask ff1/ff2 weights, merge ta+tb, transpose to [k][u] with
//    padded dims, into __device__ scratch (run every launch; deterministic).
//  - Main phase: 128 CTAs x 256 threads; CTA b handles batch rows 2b,2b+1 and
//    runs the full 1024-step recurrence. Layer2 + 2/3 of layer1 weights + fc
//    cached in smem (~224 KB); layer0 + 1 layer1 matrix streamed from L2.
// ============================================================================

// ---- Layer dims ----
#define F0 128
#define U0 135
#define C0 263
#define CP0 264
#define UP0 136
#define F1 135
#define U1 89
#define C1 224
#define CP1 224
#define UP1 92
#define F2 89
#define U2 32
#define C2 121
#define CP2 128
#define UP2 32

#define L0_MAT (CP0*UP0)          // 35904
#define L1_MAT (CP1*UP1)          // 20608
#define L2_MAT (CP2*UP2)          // 4096
#define OFF_W0 0
#define OFF_W1 (3*L0_MAT)         // 107712
#define OFF_W2 (OFF_W1 + 3*L1_MAT) // 169536
#define TOT_W  (OFF_W2 + 3*L2_MAT) // 181824

#define OFF_B0 0
#define OFF_B1 (3*UP0)            // 408
#define OFF_B2 (OFF_B1 + 3*UP1)   // 684
#define TOT_B  (OFF_B2 + 3*UP2)   // 780

__device__ float g_w[TOT_W];
__device__ float g_b[TOT_B];

// ---- Pack kernel: per layer, build 3 matrices [CP][UP] transposed+masked ----
template<int C, int CP, int U, int UP>
__global__ void pack_kernel(int woff, int boff,
    const float* __restrict__ ff1w, const float* __restrict__ ff1b,
    const float* __restrict__ ff2w, const float* __restrict__ ff2b,
    const float* __restrict__ taw,  const float* __restrict__ tab,
    const float* __restrict__ tbw,  const float* __restrict__ tbb,
    const int*   __restrict__ mask)
{
    const int n = 3 * CP * UP;
    for (int idx = blockIdx.x * blockDim.x + threadIdx.x; idx < n;
         idx += gridDim.x * blockDim.x) {
        int mat = idx / (CP * UP);
        int rem = idx - mat * (CP * UP);
        int c = rem / UP;
        int u = rem - c * UP;
        float v = 0.f;
        if (c < C && u < U) {
            int src = u * C + c;
            if (mat == 0)      v = ff1w[src] * (float)mask[src];
            else if (mat == 1) v = ff2w[src] * (float)mask[src];
            else               v = taw[src] + tbw[src];
        }
        g_w[woff + idx] = v;
    }
    for (int idx = blockIdx.x * blockDim.x + threadIdx.x; idx < 3 * UP;
         idx += gridDim.x * blockDim.x) {
        int mat = idx / UP;
        int u = idx - mat * UP;
        float v = 0.f;
        if (u < U) v = (mat == 0) ? ff1b[u] : (mat == 1 ? ff2b[u] : (tab[u] + tbb[u]));
        g_b[boff + idx] = v;
    }
}

// ---- Per-cell task phase: 3*U dot products over CP, 2 batch rows each ----
template<int CP, int U, int UP>
__device__ __forceinline__ void cell_tasks(
    const float* __restrict__ w0, const float* __restrict__ w1,
    const float* __restrict__ w2, const float* __restrict__ bias,
    const float* __restrict__ z, int zstride,
    float* __restrict__ act, int tid)
{
    const float4* za = reinterpret_cast<const float4*>(z);
    const float4* zb = reinterpret_cast<const float4*>(z + zstride);
    for (int task = tid; task < 3 * U; task += 256) {
        int mat = task / U;
        int u = task - mat * U;
        const float* w = (mat == 0) ? w0 : ((mat == 1) ? w1 : w2);
        const float* wp = w + u;
        float b = bias[mat * UP + u];
        float a0 = b, a1 = b;
#pragma unroll 4
        for (int k4 = 0; k4 < CP / 4; ++k4) {
            float4 va = za[k4];
            float4 vb = zb[k4];
            float v0 = wp[0];
            float v1 = wp[UP];
            float v2 = wp[2 * UP];
            float v3 = wp[3 * UP];
            wp += 4 * UP;
            a0 = fmaf(v0, va.x, a0); a1 = fmaf(v0, vb.x, a1);
            a0 = fmaf(v1, va.y, a0); a1 = fmaf(v1, vb.y, a1);
            a0 = fmaf(v2, va.z, a0); a1 = fmaf(v2, vb.z, a1);
            a0 = fmaf(v3, va.w, a0); a1 = fmaf(v3, vb.w, a1);
        }
        if (mat < 2) { a0 = tanhf(a0); a1 = tanhf(a1); }
        act[(mat * 2 + 0) * 136 + u] = a0;
        act[(mat * 2 + 1) * 136 + u] = a1;
    }
}

// smem layout (floats)
#define S_L1   0
#define S_L2   (S_L1 + 2*L1_MAT)     // 41216
#define S_FCW  (S_L2 + 3*L2_MAT)     // 53504
#define S_FCB  (S_FCW + 1024)        // 54528
#define S_B    (S_FCB + 32)          // 54560
#define S_Z0   (S_B + TOT_B)         // 55340
#define S_Z1   (S_Z0 + 2*CP0)        // 55868
#define S_Z2   (S_Z1 + 2*CP1)        // 56316
#define S_ACT  (S_Z2 + 2*CP2)        // 56572
#define S_TOT  (S_ACT + 6*136)       // 57388 floats = 229552 B

__global__ __launch_bounds__(256, 1)
void lnn_main(const float* __restrict__ x, const float* __restrict__ fcw,
              const float* __restrict__ fcb, float* __restrict__ out)
{
    extern __shared__ float sm[];
    float* sL1 = sm + S_L1;
    float* sL2 = sm + S_L2;
    float* sfcw = sm + S_FCW;
    float* sfcb = sm + S_FCB;
    float* sb  = sm + S_B;
    float* z0  = sm + S_Z0;
    float* z1  = sm + S_Z1;
    float* z2  = sm + S_Z2;
    float* act = sm + S_ACT;

    const int tid = threadIdx.x;

    // Fill caches
    for (int i = tid; i < 2 * L1_MAT; i += 256) sL1[i] = g_w[OFF_W1 + i];
    for (int i = tid; i < 3 * L2_MAT; i += 256) sL2[i] = g_w[OFF_W2 + i];
    for (int i = tid; i < 1024; i += 256)       sfcw[i] = fcw[i];
    if (tid < 32)                               sfcb[tid] = fcb[tid];
    for (int i = tid; i < TOT_B; i += 256)      sb[i] = g_b[i];
    // Zero z buffers (h init = 0, zero pads so padded weight rows stay inert)
    for (int i = tid; i < 2 * CP0; i += 256) z0[i] = 0.f;
    for (int i = tid; i < 2 * CP1; i += 256) z1[i] = 0.f;
    for (int i = tid; i < 2 * CP2; i += 256) z2[i] = 0.f;
    __syncthreads();

    const int b0 = blockIdx.x * 2;
    const float* xb = x + (size_t)b0 * 1024 * F0;

    for (int t = 0; t < 1024; ++t) {
        // Load x_t for both rows (256 threads = 2 rows * 128 features)
        {
            int r = tid >> 7, i = tid & 127;
            z0[r * CP0 + i] = xb[((size_t)r * 1024 + t) * F0 + i];
        }
        __syncthreads();

        // ---- Cell 0 (streamed from L2) ----
        cell_tasks<CP0, U0, UP0>(g_w + OFF_W0, g_w + OFF_W0 + L0_MAT,
                                 g_w + OFF_W0 + 2 * L0_MAT,
                                 sb + OFF_B0, z0, CP0, act, tid);
        __syncthreads();
        for (int u = tid; u < U0; u += 256) {
#pragma unroll
            for (int r = 0; r < 2; ++r) {
                float ff1 = act[(0 + r) * 136 + u];
                float ff2 = act[(2 + r) * 136 + u];
                float tt  = act[(4 + r) * 136 + u];
                float s = 1.f / (1.f + expf(-tt));
                float h = ff1 + s * (ff2 - ff1);
                z0[r * CP0 + F0 + u] = h;   // self-recurrence
                z1[r * CP1 + u]      = h;   // next cell input
            }
        }
        __syncthreads();

        // ---- Cell 1 (mats 0,1 in smem; mat 2 streamed) ----
        cell_tasks<CP1, U1, UP1>(sL1, sL1 + L1_MAT,
                                 g_w + OFF_W1 + 2 * L1_MAT,
                                 sb + OFF_B1, z1, CP1, act, tid);
        __syncthreads();
        for (int u = tid; u < U1; u += 256) {
#pragma unroll
            for (int r = 0; r < 2; ++r) {
                float ff1 = act[(0 + r) * 136 + u];
                float ff2 = act[(2 + r) * 136 + u];
                float tt  = act[(4 + r) * 136 + u];
                float s = 1.f / (1.f + expf(-tt));
                float h = ff1 + s * (ff2 - ff1);
                z1[r * CP1 + F1 + u] = h;
                z2[r * CP2 + u]      = h;
            }
        }
        __syncthreads();

        // ---- Cell 2 (fully smem-resident) ----
        cell_tasks<CP2, U2, UP2>(sL2, sL2 + L2_MAT, sL2 + 2 * L2_MAT,
                                 sb + OFF_B2, z2, CP2, act, tid);
        __syncthreads();
        for (int u = tid; u < U2; u += 256) {
#pragma unroll
            for (int r = 0; r < 2; ++r) {
                float ff1 = act[(0 + r) * 136 + u];
                float ff2 = act[(2 + r) * 136 + u];
                float tt  = act[(4 + r) * 136 + u];
                float s = 1.f / (1.f + expf(-tt));
                float h = ff1 + s * (ff2 - ff1);
                z2[r * CP2 + F2 + u] = h;
            }
        }
        __syncthreads();

        // ---- Output head: pool(identity) + fc, write [b, t, 32] ----
        if (tid < 64) {
            int r = tid >> 5, o = tid & 31;
            float y = sfcb[o];
#pragma unroll
            for (int u = 0; u < 32; ++u)
                y = fmaf(sfcw[o * 32 + u], z2[r * CP2 + F2 + u], y);
            out[(((size_t)(b0 + r)) * 1024 + t) * 32 + o] = y;
        }
        __syncthreads();
    }
}

// ============================================================================
extern "C" void kernel_launch(void* const* d_in, const int* in_sizes, int n_in,
                              void* d_out, int out_size)
{
    (void)n_in; (void)out_size;
    // Input ordering: detect interleaved-mask (setup_inputs dict order) vs
    // signature order via in_sizes[9] (mask0 has 35505 elements = l0_ff1_w).
    int base[3], mi[3], fwi, fbi;
    if (in_sizes[9] == U0 * C0) {          // interleaved: x, l0*8, mask0, l1*8, mask1, l2*8, mask2, fc_w, fc_b
        base[0] = 1;  mi[0] = 9;
        base[1] = 10; mi[1] = 18;
        base[2] = 19; mi[2] = 27;
        fwi = 28; fbi = 29;
    } else {                                // signature: x, l0*8, l1*8, l2*8, fc_w, fc_b, mask0..2
        base[0] = 1; base[1] = 9; base[2] = 17;
        fwi = 25; fbi = 26;
        mi[0] = 27; mi[1] = 28; mi[2] = 29;
    }

    const float* xin = (const float*)d_in[0];
    const float* fcw = (const float*)d_in[fwi];
    const float* fcb = (const float*)d_in[fbi];

#define LPTRS(l) \
    (const float*)d_in[base[l]+0], (const float*)d_in[base[l]+1], \
    (const float*)d_in[base[l]+2], (const float*)d_in[base[l]+3], \
    (const float*)d_in[base[l]+4], (const float*)d_in[base[l]+5], \
    (const float*)d_in[base[l]+6], (const float*)d_in[base[l]+7], \
    (const int*)d_in[mi[l]]

    pack_kernel<C0, CP0, U0, UP0><<<(3 * L0_MAT + 255) / 256, 256>>>(OFF_W0, OFF_B0, LPTRS(0));
    pack_kernel<C1, CP1, U1, UP1><<<(3 * L1_MAT + 255) / 256, 256>>>(OFF_W1, OFF_B1, LPTRS(1));
    pack_kernel<C2, CP2, U2, UP2><<<(3 * L2_MAT + 255) / 256, 256>>>(OFF_W2, OFF_B2, LPTRS(2));
#undef LPTRS

    static_assert(S_TOT * 4 <= 232448, "smem over budget");
    cudaFuncSetAttribute(lnn_main, cudaFuncAttributeMaxDynamicSharedMemorySize,
                         S_TOT * 4);
    lnn_main<<<128, 256, S_TOT * 4>>>(xin, fcw, fcb, (float*)d_out);
}

// round 9
// speedup vs baseline: 1.5331x; 1.5331x over previous
#include <cuda_runtime.h>
#include <cuda_bf16.h>

// ============================================================================
// CfC Liquid Neural Network, B=256, T=1024. Round 8.
//  - Weights repacked to float4 tiles [k/4][u] (masked ff1/ff2, merged ta+tb).
//  - 128 CTAs x 512 threads; CTA owns 2 batch rows, full 1024-step recurrence.
//  - Tasks = (mat, u-block of 2, k-chunk): vectorized loads, partial sums in
//    smem, activation applied in reduction epilogue.
//  - fc head hoisted out of the recurrence into a separate elementwise kernel.
// ============================================================================

#define F0 128
#define U0 135
#define C0 263
#define CP0 264
#define UP0 136
#define F1 135
#define U1 89
#define C1 224
#define CP1 224
#define UP1 92
#define F2 89
#define U2 32
#define C2 121
#define CP2 128
#define UP2 32

#define L0_MAT (CP0*UP0)            // 35904 floats
#define L1_MAT (CP1*UP1)            // 20608
#define L2_MAT (CP2*UP2)            // 4096
#define OFF_W0 0
#define OFF_W1 (3*L0_MAT)           // 107712
#define OFF_W2 (OFF_W1 + 3*L1_MAT)  // 169536
#define TOT_W  (OFF_W2 + 3*L2_MAT)  // 181824

#define OFF_B0 0
#define OFF_B1 (3*UP0)              // 408
#define OFF_B2 (OFF_B1 + 3*UP1)     // 684
#define TOT_B  (OFF_B2 + 3*UP2)     // 780

__device__ __align__(16) float g_w[TOT_W];
__device__ float g_b[TOT_B];

// ---- Pack: float index within a mat = ((k/4)*UP + u)*4 + (k%4) ----
template<int C, int CP, int U, int UP>
__global__ void pack_kernel(int woff, int boff,
    const float* __restrict__ ff1w, const float* __restrict__ ff1b,
    const float* __restrict__ ff2w, const float* __restrict__ ff2b,
    const float* __restrict__ taw,  const float* __restrict__ tab,
    const float* __restrict__ tbw,  const float* __restrict__ tbb,
    const int*   __restrict__ mask)
{
    const int per = CP * UP;
    const int n = 3 * per;
    for (int idx = blockIdx.x * blockDim.x + threadIdx.x; idx < n;
         idx += gridDim.x * blockDim.x) {
        int mat = idx / per;
        int e = idx - mat * per;
        int kr = e & 3;
        int t1 = e >> 2;
        int u = t1 % UP;
        int k4 = t1 / UP;
        int c = 4 * k4 + kr;
        float v = 0.f;
        if (c < C && u < U) {
            int src = u * C + c;
            if (mat == 0)      v = ff1w[src] * (float)mask[src];
            else if (mat == 1) v = ff2w[src] * (float)mask[src];
            else               v = taw[src] + tbw[src];
        }
        g_w[woff + idx] = v;
    }
    for (int idx = blockIdx.x * blockDim.x + threadIdx.x; idx < 3 * UP;
         idx += gridDim.x * blockDim.x) {
        int mat = idx / UP;
        int u = idx - mat * UP;
        float v = 0.f;
        if (u < U) v = (mat == 0) ? ff1b[u] : (mat == 1 ? ff2b[u] : (tab[u] + tbb[u]));
        g_b[boff + idx] = v;
    }
}

// ---- Dot task: 2 units x 2 rows over k4 range [kb, ke) ----
template<int UP>
__device__ __forceinline__ void dot_task(
    const float4* __restrict__ w4,
    const float4* __restrict__ za, const float4* __restrict__ zb,
    int u0, int kb, int ke,
    float& a00, float& a01, float& a10, float& a11)
{
    const float4* wp = w4 + (size_t)kb * UP + u0;
#pragma unroll 4
    for (int k4 = kb; k4 < ke; ++k4) {
        float4 w0 = wp[0];
        float4 w1 = wp[1];
        wp += UP;
        float4 va = za[k4];
        float4 vb = zb[k4];
        a00 = fmaf(w0.x, va.x, a00); a10 = fmaf(w1.x, va.x, a10);
        a01 = fmaf(w0.x, vb.x, a01); a11 = fmaf(w1.x, vb.x, a11);
        a00 = fmaf(w0.y, va.y, a00); a10 = fmaf(w1.y, va.y, a10);
        a01 = fmaf(w0.y, vb.y, a01); a11 = fmaf(w1.y, vb.y, a11);
        a00 = fmaf(w0.z, va.z, a00); a10 = fmaf(w1.z, va.z, a10);
        a01 = fmaf(w0.z, vb.z, a01); a11 = fmaf(w1.z, vb.z, a11);
        a00 = fmaf(w0.w, va.w, a00); a10 = fmaf(w1.w, va.w, a10);
        a01 = fmaf(w0.w, vb.w, a01); a11 = fmaf(w1.w, vb.w, a11);
    }
}

// smem layout (floats; all offsets multiple of 4 for float4 views)
#define S_L1   0
#define S_L2   (S_L1 + 2*L1_MAT)     // 41216
#define S_B    (S_L2 + 3*L2_MAT)     // 53504
#define S_Z0   (S_B + TOT_B)         // 54284
#define S_Z1   (S_Z0 + 2*CP0)        // 54812
#define S_Z2   (S_Z1 + 2*CP1)        // 55260
#define S_ACT  (S_Z2 + 2*CP2)        // 55516
#define S_TOT  (S_ACT + 3*2*2*UP0)   // 57148 floats = 228592 B

__global__ __launch_bounds__(512, 1)
void lnn_main(const float* __restrict__ x, float* __restrict__ out)
{
    extern __shared__ float sm[];
    float* sb  = sm + S_B;
    float* z0  = sm + S_Z0;
    float* z1  = sm + S_Z1;
    float* z2  = sm + S_Z2;
    float* act = sm + S_ACT;
    const float4* sL1v = reinterpret_cast<const float4*>(sm + S_L1);
    const float4* sL2v = reinterpret_cast<const float4*>(sm + S_L2);
    float4* z0v = reinterpret_cast<float4*>(z0);
    const float4* z1v = reinterpret_cast<const float4*>(z1);
    const float4* z2v = reinterpret_cast<const float4*>(z2);
    const float4* gw4 = reinterpret_cast<const float4*>(g_w);

    const int tid = threadIdx.x;

    // Fill smem caches
    for (int i = tid; i < 2 * L1_MAT; i += 512) sm[S_L1 + i] = g_w[OFF_W1 + i];
    for (int i = tid; i < 3 * L2_MAT; i += 512) sm[S_L2 + i] = g_w[OFF_W2 + i];
    for (int i = tid; i < TOT_B; i += 512)      sb[i] = g_b[i];
    for (int i = tid; i < 2 * CP0; i += 512) z0[i] = 0.f;
    for (int i = tid; i < 2 * CP1; i += 512) z1[i] = 0.f;
    for (int i = tid; i < 2 * CP2; i += 512) z2[i] = 0.f;
    __syncthreads();

    const int b0 = blockIdx.x * 2;
    const float4* xv = reinterpret_cast<const float4*>(x) + (size_t)b0 * 1024 * 32;
    const int xr = tid >> 5, xi = tid & 31;   // for tid < 64

    float4 xreg = make_float4(0.f, 0.f, 0.f, 0.f);
    if (tid < 64) xreg = xv[((size_t)xr * 1024 + 0) * 32 + xi];

    for (int t = 0; t < 1024; ++t) {
        // store current x_t into z0; prefetch next
        if (tid < 64) z0v[xr * (CP0 / 4) + xi] = xreg;
        __syncthreads();
        if (tid < 64) {
            int tn = (t + 1 < 1024) ? t + 1 : t;
            xreg = xv[((size_t)xr * 1024 + tn) * 32 + xi];
        }

        // ======== Cell 0: streamed weights. tasks = 3 mats x 68 ublk x 2 ks
        if (tid < 408) {
            int ub = tid % 68, q = tid / 68;
            int ks = q & 1, mat = q >> 1;
            int u0 = 2 * ub;
            float b0v = 0.f, b1v = 0.f;
            if (ks == 0) { b0v = sb[OFF_B0 + mat * UP0 + u0]; b1v = sb[OFF_B0 + mat * UP0 + u0 + 1]; }
            float a00 = b0v, a01 = b0v, a10 = b1v, a11 = b1v;
            int kb = ks * 33, ke = kb + 33;
            dot_task<UP0>(gw4 + (OFF_W0 / 4) + mat * (L0_MAT / 4),
                          z0v, z0v + (CP0 / 4), u0, kb, ke, a00, a01, a10, a11);
            float* ap = act + ((mat * 2 + ks) * 2) * UP0;
            reinterpret_cast<float2*>(ap + u0)[0]       = make_float2(a00, a10);
            reinterpret_cast<float2*>(ap + UP0 + u0)[0] = make_float2(a01, a11);
        }
        __syncthreads();
        // epi0: reduce ks, activations, write h0
        for (int u = tid; u < U0; u += 512) {
#pragma unroll
            for (int r = 0; r < 2; ++r) {
                float f1 = tanhf(act[(0 * 2 + 0) * 2 * UP0 + r * UP0 + u] + act[(0 * 2 + 1) * 2 * UP0 + r * UP0 + u]);
                float f2 = tanhf(act[(1 * 2 + 0) * 2 * UP0 + r * UP0 + u] + act[(1 * 2 + 1) * 2 * UP0 + r * UP0 + u]);
                float tt =       act[(2 * 2 + 0) * 2 * UP0 + r * UP0 + u] + act[(2 * 2 + 1) * 2 * UP0 + r * UP0 + u];
                float s = 1.f / (1.f + expf(-tt));
                float h = f1 + s * (f2 - f1);
                z0[r * CP0 + F0 + u] = h;
                z1[r * CP1 + u]      = h;
            }
        }
        __syncthreads();

        // ======== Cell 1: mats 0,1 smem; mat 2 streamed. tasks = 3 x 45 x 2
        if (tid < 270) {
            int ub = tid % 45, q = tid / 45;
            int ks = q & 1, mat = q >> 1;
            int u0 = 2 * ub;
            float b0v = 0.f, b1v = 0.f;
            if (ks == 0) { b0v = sb[OFF_B1 + mat * UP1 + u0]; b1v = sb[OFF_B1 + mat * UP1 + u0 + 1]; }
            float a00 = b0v, a01 = b0v, a10 = b1v, a11 = b1v;
            int kb = ks * 28, ke = kb + 28;
            if (mat < 2)
                dot_task<UP1>(sL1v + mat * (L1_MAT / 4),
                              z1v, z1v + (CP1 / 4), u0, kb, ke, a00, a01, a10, a11);
            else
                dot_task<UP1>(gw4 + (OFF_W1 / 4) + 2 * (L1_MAT / 4),
                              z1v, z1v + (CP1 / 4), u0, kb, ke, a00, a01, a10, a11);
            float* ap = act + ((mat * 2 + ks) * 2) * UP1;
            reinterpret_cast<float2*>(ap + u0)[0]       = make_float2(a00, a10);
            reinterpret_cast<float2*>(ap + UP1 + u0)[0] = make_float2(a01, a11);
        }
        __syncthreads();
        for (int u = tid; u < U1; u += 512) {
#pragma unroll
            for (int r = 0; r < 2; ++r) {
                float f1 = tanhf(act[(0 * 2 + 0) * 2 * UP1 + r * UP1 + u] + act[(0 * 2 + 1) * 2 * UP1 + r * UP1 + u]);
                float f2 = tanhf(act[(1 * 2 + 0) * 2 * UP1 + r * UP1 + u] + act[(1 * 2 + 1) * 2 * UP1 + r * UP1 + u]);
                float tt =       act[(2 * 2 + 0) * 2 * UP1 + r * UP1 + u] + act[(2 * 2 + 1) * 2 * UP1 + r * UP1 + u];
                float s = 1.f / (1.f + expf(-tt));
                float h = f1 + s * (f2 - f1);
                z1[r * CP1 + F1 + u] = h;
                z2[r * CP2 + u]      = h;
            }
        }
        __syncthreads();

        // ======== Cell 2: all smem. tasks = 3 x 16 x 4
        if (tid < 192) {
            int ub = tid & 15, q = tid >> 4;
            int ks = q & 3, mat = q >> 2;
            int u0 = 2 * ub;
            float b0v = 0.f, b1v = 0.f;
            if (ks == 0) { b0v = sb[OFF_B2 + mat * UP2 + u0]; b1v = sb[OFF_B2 + mat * UP2 + u0 + 1]; }
            float a00 = b0v, a01 = b0v, a10 = b1v, a11 = b1v;
            int kb = ks * 8, ke = kb + 8;
            dot_task<UP2>(sL2v + mat * (L2_MAT / 4),
                          z2v, z2v + (CP2 / 4), u0, kb, ke, a00, a01, a10, a11);
            float* ap = act + ((mat * 4 + ks) * 2) * UP2;
            reinterpret_cast<float2*>(ap + u0)[0]       = make_float2(a00, a10);
            reinterpret_cast<float2*>(ap + UP2 + u0)[0] = make_float2(a01, a11);
        }
        __syncthreads();
        if (tid < U2) {
            int u = tid;
#pragma unroll
            for (int r = 0; r < 2; ++r) {
                float f1 = act[(0 * 4 + 0) * 2 * UP2 + r * UP2 + u] + act[(0 * 4 + 1) * 2 * UP2 + r * UP2 + u]
                         + act[(0 * 4 + 2) * 2 * UP2 + r * UP2 + u] + act[(0 * 4 + 3) * 2 * UP2 + r * UP2 + u];
                float f2 = act[(1 * 4 + 0) * 2 * UP2 + r * UP2 + u] + act[(1 * 4 + 1) * 2 * UP2 + r * UP2 + u]
                         + act[(1 * 4 + 2) * 2 * UP2 + r * UP2 + u] + act[(1 * 4 + 3) * 2 * UP2 + r * UP2 + u];
                float tt = act[(2 * 4 + 0) * 2 * UP2 + r * UP2 + u] + act[(2 * 4 + 1) * 2 * UP2 + r * UP2 + u]
                         + act[(2 * 4 + 2) * 2 * UP2 + r * UP2 + u] + act[(2 * 4 + 3) * 2 * UP2 + r * UP2 + u];
                f1 = tanhf(f1); f2 = tanhf(f2);
                float s = 1.f / (1.f + expf(-tt));
                float h = f1 + s * (f2 - f1);
                z2[r * CP2 + F2 + u] = h;
                out[(((size_t)(b0 + r)) * 1024 + t) * 32 + u] = h;  // h2 -> out (fc applied later)
            }
        }
        __syncthreads();
    }
}

// ---- fc head applied in place over out[256*1024][32] ----
__global__ __launch_bounds__(256)
void fc_kernel(float* __restrict__ out, const float* __restrict__ fcw,
               const float* __restrict__ fcb)
{
    __shared__ float w[1024];
    __shared__ float b[32];
    int tid = threadIdx.x;
    for (int i = tid; i < 1024; i += 256) w[i] = fcw[i];
    if (tid < 32) b[tid] = fcb[tid];
    __syncthreads();

    size_t pos = (size_t)blockIdx.x * 256 + tid;   // 262144 positions
    float4* p = reinterpret_cast<float4*>(out) + pos * 8;
    float h[32];
    float4 v[8];
#pragma unroll
    for (int i = 0; i < 8; ++i) v[i] = p[i];
#pragma unroll
    for (int i = 0; i < 8; ++i) {
        h[4 * i + 0] = v[i].x; h[4 * i + 1] = v[i].y;
        h[4 * i + 2] = v[i].z; h[4 * i + 3] = v[i].w;
    }
#pragma unroll
    for (int i = 0; i < 8; ++i) {
        float y[4];
#pragma unroll
        for (int j = 0; j < 4; ++j) {
            int o = 4 * i + j;
            float acc = b[o];
#pragma unroll
            for (int u = 0; u < 32; ++u) acc = fmaf(w[o * 32 + u], h[u], acc);
            y[j] = acc;
        }
        p[i] = make_float4(y[0], y[1], y[2], y[3]);
    }
}

// ============================================================================
extern "C" void kernel_launch(void* const* d_in, const int* in_sizes, int n_in,
                              void* d_out, int out_size)
{
    (void)n_in; (void)out_size;
    int base[3], mi[3], fwi, fbi;
    if (in_sizes[9] == U0 * C0) {          // interleaved dict order
        base[0] = 1;  mi[0] = 9;
        base[1] = 10; mi[1] = 18;
        base[2] = 19; mi[2] = 27;
        fwi = 28; fbi = 29;
    } else {                                // signature order
        base[0] = 1; base[1] = 9; base[2] = 17;
        fwi = 25; fbi = 26;
        mi[0] = 27; mi[1] = 28; mi[2] = 29;
    }

    const float* xin = (const float*)d_in[0];
    const float* fcw = (const float*)d_in[fwi];
    const float* fcb = (const float*)d_in[fbi];

#define LPTRS(l) \
    (const float*)d_in[base[l]+0], (const float*)d_in[base[l]+1], \
    (const float*)d_in[base[l]+2], (const float*)d_in[base[l]+3], \
    (const float*)d_in[base[l]+4], (const float*)d_in[base[l]+5], \
    (const float*)d_in[base[l]+6], (const float*)d_in[base[l]+7], \
    (const int*)d_in[mi[l]]

    pack_kernel<C0, CP0, U0, UP0><<<(3 * L0_MAT + 255) / 256, 256>>>(OFF_W0, OFF_B0, LPTRS(0));
    pack_kernel<C1, CP1, U1, UP1><<<(3 * L1_MAT + 255) / 256, 256>>>(OFF_W1, OFF_B1, LPTRS(1));
    pack_kernel<C2, CP2, U2, UP2><<<(3 * L2_MAT + 255) / 256, 256>>>(OFF_W2, OFF_B2, LPTRS(2));
#undef LPTRS

    static_assert(S_TOT * 4 <= 232448, "smem over budget");
    cudaFuncSetAttribute(lnn_main, cudaFuncAttributeMaxDynamicSharedMemorySize,
                         S_TOT * 4);
    lnn_main<<<128, 512, S_TOT * 4>>>(xin, (float*)d_out);
    fc_kernel<<<1024, 256>>>((float*)d_out, fcw, fcb);
}

// round 10
// speedup vs baseline: 2.8310x; 1.8466x over previous
#include <cuda_runtime.h>
#include <cuda_fp16.h>

// ============================================================================
// CfC Liquid Neural Network, B=256, T=1024. Round 9.
//  - fp16 weights (fp32 z / fp32 accumulation), packed as half2 (k,k+1) tiles
//    laid out [k2][u]; uint4 load = 4 units x 2 k.
//  - 128 CTAs x 512 threads, 2 batch rows per CTA, 1024-step recurrence.
//  - cell1 + cell2 weights fully smem-resident (fp16); cell0 streamed from L2.
//  - UB=4 u-blocking + k-splitting (4/7/16) for occupancy + MLP.
//  - fc head applied by a separate elementwise kernel after the recurrence.
// ============================================================================

#define F0 128
#define U0 135
#define C0 263
#define CP0 264
#define UP0 136
#define F1 135
#define U1 89
#define C1 224
#define CP1 224
#define UP1 92
#define F2 89
#define U2 32
#define C2 121
#define CP2 128
#define UP2 32

#define L0_MAT (CP0*UP0)            // 35904 halves per mat
#define L1_MAT (CP1*UP1)            // 20608
#define L2_MAT (CP2*UP2)            // 4096
#define OFF_W0 0
#define OFF_W1 (3*L0_MAT)           // 107712
#define OFF_W2 (OFF_W1 + 3*L1_MAT)  // 169536
#define TOT_W  (OFF_W2 + 3*L2_MAT)  // 181824

#define OFF_B0 0
#define OFF_B1 (3*UP0)              // 408
#define OFF_B2 (OFF_B1 + 3*UP1)     // 684
#define TOT_B  (OFF_B2 + 3*UP2)     // 780

__device__ __align__(16) __half g_wh[TOT_W];
__device__ float g_b[TOT_B];

// ---- Pack: half linear idx within mat = (k2*UP + u)*2 + r, k = 2*k2 + r ----
template<int C, int CP, int U, int UP>
__global__ void pack_kernel(int woff, int boff,
    const float* __restrict__ ff1w, const float* __restrict__ ff1b,
    const float* __restrict__ ff2w, const float* __restrict__ ff2b,
    const float* __restrict__ taw,  const float* __restrict__ tab,
    const float* __restrict__ tbw,  const float* __restrict__ tbb,
    const int*   __restrict__ mask)
{
    const int per = CP * UP;
    const int n = 3 * per;
    for (int idx = blockIdx.x * blockDim.x + threadIdx.x; idx < n;
         idx += gridDim.x * blockDim.x) {
        int mat = idx / per;
        int e = idx - mat * per;
        int r = e & 1;
        int t1 = e >> 1;
        int u = t1 % UP;
        int k2 = t1 / UP;
        int c = 2 * k2 + r;
        float v = 0.f;
        if (c < C && u < U) {
            int src = u * C + c;
            if (mat == 0)      v = ff1w[src] * (float)mask[src];
            else if (mat == 1) v = ff2w[src] * (float)mask[src];
            else               v = taw[src] + tbw[src];
        }
        g_wh[woff + idx] = __float2half_rn(v);
    }
    for (int idx = blockIdx.x * blockDim.x + threadIdx.x; idx < 3 * UP;
         idx += gridDim.x * blockDim.x) {
        int mat = idx / UP;
        int u = idx - mat * UP;
        float v = 0.f;
        if (u < U) v = (mat == 0) ? ff1b[u] : (mat == 1 ? ff2b[u] : (tab[u] + tbb[u]));
        g_b[boff + idx] = v;
    }
}

// ---- Dot task: 4 units x 2 rows over k4 range [kb, ke). acc[2*u + row] ----
template<int UP>
__device__ __forceinline__ void dot_h(
    const uint4* __restrict__ wbase,
    const float4* __restrict__ za, const float4* __restrict__ zb,
    int ub, int kb, int ke, float acc[8])
{
    const uint4* wp = wbase + (size_t)(2 * kb) * (UP / 4) + ub;
#pragma unroll 4
    for (int k4 = kb; k4 < ke; ++k4) {
        uint4 wa = wp[0];
        uint4 wc = wp[UP / 4];
        wp += UP / 2;
        float4 va = za[k4];
        float4 vb = zb[k4];
        float2 c;
        // k, k+1 (wa), units 0..3
        c = __half22float2(*(const __half2*)&wa.x);
        acc[0] = fmaf(c.x, va.x, acc[0]); acc[0] = fmaf(c.y, va.y, acc[0]);
        acc[1] = fmaf(c.x, vb.x, acc[1]); acc[1] = fmaf(c.y, vb.y, acc[1]);
        c = __half22float2(*(const __half2*)&wa.y);
        acc[2] = fmaf(c.x, va.x, acc[2]); acc[2] = fmaf(c.y, va.y, acc[2]);
        acc[3] = fmaf(c.x, vb.x, acc[3]); acc[3] = fmaf(c.y, vb.y, acc[3]);
        c = __half22float2(*(const __half2*)&wa.z);
        acc[4] = fmaf(c.x, va.x, acc[4]); acc[4] = fmaf(c.y, va.y, acc[4]);
        acc[5] = fmaf(c.x, vb.x, acc[5]); acc[5] = fmaf(c.y, vb.y, acc[5]);
        c = __half22float2(*(const __half2*)&wa.w);
        acc[6] = fmaf(c.x, va.x, acc[6]); acc[6] = fmaf(c.y, va.y, acc[6]);
        acc[7] = fmaf(c.x, vb.x, acc[7]); acc[7] = fmaf(c.y, vb.y, acc[7]);
        // k+2, k+3 (wc), units 0..3
        c = __half22float2(*(const __half2*)&wc.x);
        acc[0] = fmaf(c.x, va.z, acc[0]); acc[0] = fmaf(c.y, va.w, acc[0]);
        acc[1] = fmaf(c.x, vb.z, acc[1]); acc[1] = fmaf(c.y, vb.w, acc[1]);
        c = __half22float2(*(const __half2*)&wc.y);
        acc[2] = fmaf(c.x, va.z, acc[2]); acc[2] = fmaf(c.y, va.w, acc[2]);
        acc[3] = fmaf(c.x, vb.z, acc[3]); acc[3] = fmaf(c.y, vb.w, acc[3]);
        c = __half22float2(*(const __half2*)&wc.z);
        acc[4] = fmaf(c.x, va.z, acc[4]); acc[4] = fmaf(c.y, va.w, acc[4]);
        acc[5] = fmaf(c.x, vb.z, acc[5]); acc[5] = fmaf(c.y, vb.w, acc[5]);
        c = __half22float2(*(const __half2*)&wc.w);
        acc[6] = fmaf(c.x, va.z, acc[6]); acc[6] = fmaf(c.y, va.w, acc[6]);
        acc[7] = fmaf(c.x, vb.z, acc[7]); acc[7] = fmaf(c.y, vb.w, acc[7]);
    }
}

// ---- smem layout (byte offsets; all multiples of 16) ----
#define SB_W1   0                            // 3*L1_MAT halves = 123648 B
#define SB_W2   (SB_W1 + 3*L1_MAT*2)         // 123648; 3*L2_MAT halves = 24576 B
#define SB_B    (SB_W2 + 3*L2_MAT*2)         // 148224; 780 floats = 3120 B
#define SB_Z0   (SB_B + TOT_B*4)             // 151344; 528 floats
#define SB_Z1   (SB_Z0 + 2*CP0*4)            // 153456; 448 floats
#define SB_Z2   (SB_Z1 + 2*CP1*4)            // 155248; 256 floats
#define SB_ACT  (SB_Z2 + 2*CP2*4)            // 156272; 3864 floats = 15456 B
#define SB_TOT  (SB_ACT + 3*7*2*UP1*4)       // 171728 B

#define KS0 4
#define KS1 7
#define KS2 16

__global__ __launch_bounds__(512, 1)
void lnn_main(const float* __restrict__ x, float* __restrict__ out)
{
    extern __shared__ __align__(16) char smraw[];
    __half* sW1 = (__half*)(smraw + SB_W1);
    __half* sW2 = (__half*)(smraw + SB_W2);
    float*  sb  = (float*)(smraw + SB_B);
    float*  z0  = (float*)(smraw + SB_Z0);
    float*  z1  = (float*)(smraw + SB_Z1);
    float*  z2  = (float*)(smraw + SB_Z2);
    float*  act = (float*)(smraw + SB_ACT);
    const uint4* sW1v = (const uint4*)sW1;
    const uint4* sW2v = (const uint4*)sW2;
    const uint4* gw0  = (const uint4*)g_wh + OFF_W0 / 8;
    float4* z0v = (float4*)z0;
    const float4* z1v = (const float4*)z1;
    const float4* z2v = (const float4*)z2;

    const int tid = threadIdx.x;

    // Fill smem caches (uint4 copies)
    {
        const uint4* gsrc = (const uint4*)g_wh;
        uint4* d1 = (uint4*)sW1;
        uint4* d2 = (uint4*)sW2;
        for (int i = tid; i < 3 * L1_MAT / 8; i += 512) d1[i] = gsrc[OFF_W1 / 8 + i];
        for (int i = tid; i < 3 * L2_MAT / 8; i += 512) d2[i] = gsrc[OFF_W2 / 8 + i];
    }
    for (int i = tid; i < TOT_B; i += 512) sb[i] = g_b[i];
    for (int i = tid; i < 2 * CP0; i += 512) z0[i] = 0.f;
    for (int i = tid; i < 2 * CP1; i += 512) z1[i] = 0.f;
    for (int i = tid; i < 2 * CP2; i += 512) z2[i] = 0.f;
    __syncthreads();

    const int b0 = blockIdx.x * 2;
    const float4* xv = (const float4*)x + (size_t)b0 * 1024 * 32;
    const int xr = tid >> 5, xi = tid & 31;   // for tid < 64

    float4 xreg = make_float4(0.f, 0.f, 0.f, 0.f);
    if (tid < 64) xreg = xv[((size_t)xr * 1024 + 0) * 32 + xi];

    for (int t = 0; t < 1024; ++t) {
        if (tid < 64) z0v[xr * (CP0 / 4) + xi] = xreg;
        __syncthreads();
        if (tid < 64) {
            int tn = (t + 1 < 1024) ? t + 1 : t;
            xreg = xv[((size_t)xr * 1024 + tn) * 32 + xi];
        }

        // ======== Cell 0 (streamed, fp16): 3 mats x 34 ublk x 4 ks = 408 tasks
        if (tid < 408) {
            int ub = tid % 34, q = tid / 34;
            int ks = q & 3, mat = q >> 2;
            int u0 = 4 * ub;
            float acc[8];
            if (ks == 0) {
#pragma unroll
                for (int u = 0; u < 4; ++u) {
                    float bv = sb[OFF_B0 + mat * UP0 + u0 + u];
                    acc[2 * u] = bv; acc[2 * u + 1] = bv;
                }
            } else {
#pragma unroll
                for (int i = 0; i < 8; ++i) acc[i] = 0.f;
            }
            int kb = (ks * 66) >> 2, ke = ((ks + 1) * 66) >> 2;
            dot_h<UP0>(gw0 + mat * (L0_MAT / 8), z0v, z0v + CP0 / 4, ub, kb, ke, acc);
            float* ap = act + ((mat * KS0 + ks) * 2) * UP0 + u0;
            *(float4*)ap         = make_float4(acc[0], acc[2], acc[4], acc[6]);
            *(float4*)(ap + UP0) = make_float4(acc[1], acc[3], acc[5], acc[7]);
        }
        __syncthreads();
        for (int u = tid; u < U0; u += 512) {
#pragma unroll
            for (int r = 0; r < 2; ++r) {
                float f1 = 0.f, f2 = 0.f, tt = 0.f;
#pragma unroll
                for (int ks = 0; ks < KS0; ++ks) {
                    f1 += act[((0 * KS0 + ks) * 2 + r) * UP0 + u];
                    f2 += act[((1 * KS0 + ks) * 2 + r) * UP0 + u];
                    tt += act[((2 * KS0 + ks) * 2 + r) * UP0 + u];
                }
                f1 = tanhf(f1); f2 = tanhf(f2);
                float s = 1.f / (1.f + expf(-tt));
                float h = f1 + s * (f2 - f1);
                z0[r * CP0 + F0 + u] = h;
                z1[r * CP1 + u]      = h;
            }
        }
        __syncthreads();

        // ======== Cell 1 (smem fp16): 3 mats x 23 ublk x 7 ks = 483 tasks
        if (tid < 483) {
            int ub = tid % 23, q = tid / 23;
            int ks = q % 7, mat = q / 7;
            int u0 = 4 * ub;
            float acc[8];
            if (ks == 0) {
#pragma unroll
                for (int u = 0; u < 4; ++u) {
                    float bv = sb[OFF_B1 + mat * UP1 + u0 + u];
                    acc[2 * u] = bv; acc[2 * u + 1] = bv;
                }
            } else {
#pragma unroll
                for (int i = 0; i < 8; ++i) acc[i] = 0.f;
            }
            int kb = ks * 8, ke = kb + 8;
            dot_h<UP1>(sW1v + mat * (L1_MAT / 8), z1v, z1v + CP1 / 4, ub, kb, ke, acc);
            float* ap = act + ((mat * KS1 + ks) * 2) * UP1 + u0;
            *(float4*)ap         = make_float4(acc[0], acc[2], acc[4], acc[6]);
            *(float4*)(ap + UP1) = make_float4(acc[1], acc[3], acc[5], acc[7]);
        }
        __syncthreads();
        for (int u = tid; u < U1; u += 512) {
#pragma unroll
            for (int r = 0; r < 2; ++r) {
                float f1 = 0.f, f2 = 0.f, tt = 0.f;
#pragma unroll
                for (int ks = 0; ks < KS1; ++ks) {
                    f1 += act[((0 * KS1 + ks) * 2 + r) * UP1 + u];
                    f2 += act[((1 * KS1 + ks) * 2 + r) * UP1 + u];
                    tt += act[((2 * KS1 + ks) * 2 + r) * UP1 + u];
                }
                f1 = tanhf(f1); f2 = tanhf(f2);
                float s = 1.f / (1.f + expf(-tt));
                float h = f1 + s * (f2 - f1);
                z1[r * CP1 + F1 + u] = h;
                z2[r * CP2 + u]      = h;
            }
        }
        __syncthreads();

        // ======== Cell 2 (smem fp16): 3 mats x 8 ublk x 16 ks = 384 tasks
        if (tid < 384) {
            int ub = tid & 7, q = tid >> 3;
            int ks = q & 15, mat = q >> 4;
            int u0 = 4 * ub;
            float acc[8];
            if (ks == 0) {
#pragma unroll
                for (int u = 0; u < 4; ++u) {
                    float bv = sb[OFF_B2 + mat * UP2 + u0 + u];
                    acc[2 * u] = bv; acc[2 * u + 1] = bv;
                }
            } else {
#pragma unroll
                for (int i = 0; i < 8; ++i) acc[i] = 0.f;
            }
            int kb = ks * 2, ke = kb + 2;
            dot_h<UP2>(sW2v + mat * (L2_MAT / 8), z2v, z2v + CP2 / 4, ub, kb, ke, acc);
            float* ap = act + ((mat * KS2 + ks) * 2) * UP2 + u0;
            *(float4*)ap         = make_float4(acc[0], acc[2], acc[4], acc[6]);
            *(float4*)(ap + UP2) = make_float4(acc[1], acc[3], acc[5], acc[7]);
        }
        __syncthreads();
        if (tid < U2) {
            int u = tid;
#pragma unroll
            for (int r = 0; r < 2; ++r) {
                float f1 = 0.f, f2 = 0.f, tt = 0.f;
#pragma unroll
                for (int ks = 0; ks < KS2; ++ks) {
                    f1 += act[((0 * KS2 + ks) * 2 + r) * UP2 + u];
                    f2 += act[((1 * KS2 + ks) * 2 + r) * UP2 + u];
                    tt += act[((2 * KS2 + ks) * 2 + r) * UP2 + u];
                }
                f1 = tanhf(f1); f2 = tanhf(f2);
                float s = 1.f / (1.f + expf(-tt));
                float h = f1 + s * (f2 - f1);
                z2[r * CP2 + F2 + u] = h;
                out[(((size_t)(b0 + r)) * 1024 + t) * 32 + u] = h;
            }
        }
        __syncthreads();
    }
}

// ---- fc head applied in place over out[256*1024][32] ----
__global__ __launch_bounds__(256)
void fc_kernel(float* __restrict__ out, const float* __restrict__ fcw,
               const float* __restrict__ fcb)
{
    __shared__ float w[1024];
    __shared__ float b[32];
    int tid = threadIdx.x;
    for (int i = tid; i < 1024; i += 256) w[i] = fcw[i];
    if (tid < 32) b[tid] = fcb[tid];
    __syncthreads();

    size_t pos = (size_t)blockIdx.x * 256 + tid;   // 262144 positions
    float4* p = reinterpret_cast<float4*>(out) + pos * 8;
    float h[32];
    float4 v[8];
#pragma unroll
    for (int i = 0; i < 8; ++i) v[i] = p[i];
#pragma unroll
    for (int i = 0; i < 8; ++i) {
        h[4 * i + 0] = v[i].x; h[4 * i + 1] = v[i].y;
        h[4 * i + 2] = v[i].z; h[4 * i + 3] = v[i].w;
    }
#pragma unroll
    for (int i = 0; i < 8; ++i) {
        float y[4];
#pragma unroll
        for (int j = 0; j < 4; ++j) {
            int o = 4 * i + j;
            float acc = b[o];
#pragma unroll
            for (int u = 0; u < 32; ++u) acc = fmaf(w[o * 32 + u], h[u], acc);
            y[j] = acc;
        }
        p[i] = make_float4(y[0], y[1], y[2], y[3]);
    }
}

// ============================================================================
extern "C" void kernel_launch(void* const* d_in, const int* in_sizes, int n_in,
                              void* d_out, int out_size)
{
    (void)n_in; (void)out_size;
    int base[3], mi[3], fwi, fbi;
    if (in_sizes[9] == U0 * C0) {          // interleaved dict order
        base[0] = 1;  mi[0] = 9;
        base[1] = 10; mi[1] = 18;
        base[2] = 19; mi[2] = 27;
        fwi = 28; fbi = 29;
    } else {                                // signature order
        base[0] = 1; base[1] = 9; base[2] = 17;
        fwi = 25; fbi = 26;
        mi[0] = 27; mi[1] = 28; mi[2] = 29;
    }

    const float* xin = (const float*)d_in[0];
    const float* fcw = (const float*)d_in[fwi];
    const float* fcb = (const float*)d_in[fbi];

#define LPTRS(l) \
    (const float*)d_in[base[l]+0], (const float*)d_in[base[l]+1], \
    (const float*)d_in[base[l]+2], (const float*)d_in[base[l]+3], \
    (const float*)d_in[base[l]+4], (const float*)d_in[base[l]+5], \
    (const float*)d_in[base[l]+6], (const float*)d_in[base[l]+7], \
    (const int*)d_in[mi[l]]

    pack_kernel<C0, CP0, U0, UP0><<<(3 * L0_MAT + 255) / 256, 256>>>(OFF_W0, OFF_B0, LPTRS(0));
    pack_kernel<C1, CP1, U1, UP1><<<(3 * L1_MAT + 255) / 256, 256>>>(OFF_W1, OFF_B1, LPTRS(1));
    pack_kernel<C2, CP2, U2, UP2><<<(3 * L2_MAT + 255) / 256, 256>>>(OFF_W2, OFF_B2, LPTRS(2));
#undef LPTRS

    static_assert(SB_TOT <= 232448, "smem over budget");
    cudaFuncSetAttribute(lnn_main, cudaFuncAttributeMaxDynamicSharedMemorySize,
                         SB_TOT);
    lnn_main<<<128, 512, SB_TOT>>>(xin, (float*)d_out);
    fc_kernel<<<1024, 256>>>((float*)d_out, fcw, fcb);
}

// round 11
// speedup vs baseline: 2.8863x; 1.0195x over previous
#include <cuda_runtime.h>
#include <cuda_fp16.h>

// ============================================================================
// CfC Liquid Neural Network, B=256, T=1024. Round 10.
//  - fp16 weights (fp32 z / fp32 accumulation) packed as half2 (k,k+1) [k2][u].
//  - NEW: packed fma.rn.f32x2 (FFMA2) — pair over k: multiplier = cvt(half2),
//    multiplicand = adjacent z pair from LDS.128, float2 accumulators.
//  - 128 CTAs x 512 threads, 2 batch rows per CTA, 1024-step recurrence.
//  - cell1+cell2 weights smem-resident; cell0 streamed from L2 (KS0=5 split).
//  - fc head applied by a separate elementwise kernel.
// ============================================================================

#define F0 128
#define U0 135
#define C0 263
#define CP0 264
#define UP0 136
#define F1 135
#define U1 89
#define C1 224
#define CP1 224
#define UP1 92
#define F2 89
#define U2 32
#define C2 121
#define CP2 128
#define UP2 32

#define L0_MAT (CP0*UP0)            // 35904 halves per mat
#define L1_MAT (CP1*UP1)            // 20608
#define L2_MAT (CP2*UP2)            // 4096
#define OFF_W0 0
#define OFF_W1 (3*L0_MAT)           // 107712
#define OFF_W2 (OFF_W1 + 3*L1_MAT)  // 169536
#define TOT_W  (OFF_W2 + 3*L2_MAT)  // 181824

#define OFF_B0 0
#define OFF_B1 (3*UP0)              // 408
#define OFF_B2 (OFF_B1 + 3*UP1)     // 684
#define TOT_B  (OFF_B2 + 3*UP2)     // 780

__device__ __align__(16) __half g_wh[TOT_W];
__device__ float g_b[TOT_B];

// ---- packed fp32x2 FMA: d = a*b + d (one SASS FFMA2 issue) ----
__device__ __forceinline__ void fma2(float2& d, const float2& a, const float2& b)
{
    unsigned long long& dv = reinterpret_cast<unsigned long long&>(d);
    asm("fma.rn.f32x2 %0, %1, %2, %0;"
        : "+l"(dv)
        : "l"(reinterpret_cast<const unsigned long long&>(a)),
          "l"(reinterpret_cast<const unsigned long long&>(b)));
}

// ---- Pack: half linear idx within mat = (k2*UP + u)*2 + r, k = 2*k2 + r ----
template<int C, int CP, int U, int UP>
__global__ void pack_kernel(int woff, int boff,
    const float* __restrict__ ff1w, const float* __restrict__ ff1b,
    const float* __restrict__ ff2w, const float* __restrict__ ff2b,
    const float* __restrict__ taw,  const float* __restrict__ tab,
    const float* __restrict__ tbw,  const float* __restrict__ tbb,
    const int*   __restrict__ mask)
{
    const int per = CP * UP;
    const int n = 3 * per;
    for (int idx = blockIdx.x * blockDim.x + threadIdx.x; idx < n;
         idx += gridDim.x * blockDim.x) {
        int mat = idx / per;
        int e = idx - mat * per;
        int r = e & 1;
        int t1 = e >> 1;
        int u = t1 % UP;
        int k2 = t1 / UP;
        int c = 2 * k2 + r;
        float v = 0.f;
        if (c < C && u < U) {
            int src = u * C + c;
            if (mat == 0)      v = ff1w[src] * (float)mask[src];
            else if (mat == 1) v = ff2w[src] * (float)mask[src];
            else               v = taw[src] + tbw[src];
        }
        g_wh[woff + idx] = __float2half_rn(v);
    }
    for (int idx = blockIdx.x * blockDim.x + threadIdx.x; idx < 3 * UP;
         idx += gridDim.x * blockDim.x) {
        int mat = idx / UP;
        int u = idx - mat * UP;
        float v = 0.f;
        if (u < U) v = (mat == 0) ? ff1b[u] : (mat == 1 ? ff2b[u] : (tab[u] + tbb[u]));
        g_b[boff + idx] = v;
    }
}

// ---- Dot task: 4 units x 2 rows over k4 range [kb, ke); float2 acc over k ----
template<int UP>
__device__ __forceinline__ void dot2(
    const uint4* __restrict__ wbase,
    const float4* __restrict__ za, const float4* __restrict__ zb,
    int ub, int kb, int ke, float2 acc[8])
{
    const uint4* wp = wbase + (size_t)(2 * kb) * (UP / 4) + ub;
#pragma unroll 4
    for (int k4 = kb; k4 < ke; ++k4) {
        uint4 wa = wp[0];
        uint4 wc = wp[UP / 4];
        wp += UP / 2;
        float4 va = za[k4];
        float4 vb = zb[k4];
        float2 a01 = make_float2(va.x, va.y), a23 = make_float2(va.z, va.w);
        float2 b01 = make_float2(vb.x, vb.y), b23 = make_float2(vb.z, vb.w);
        float2 w;
        w = __half22float2(*(const __half2*)&wa.x);
        fma2(acc[0], w, a01); fma2(acc[1], w, b01);
        w = __half22float2(*(const __half2*)&wa.y);
        fma2(acc[2], w, a01); fma2(acc[3], w, b01);
        w = __half22float2(*(const __half2*)&wa.z);
        fma2(acc[4], w, a01); fma2(acc[5], w, b01);
        w = __half22float2(*(const __half2*)&wa.w);
        fma2(acc[6], w, a01); fma2(acc[7], w, b01);
        w = __half22float2(*(const __half2*)&wc.x);
        fma2(acc[0], w, a23); fma2(acc[1], w, b23);
        w = __half22float2(*(const __half2*)&wc.y);
        fma2(acc[2], w, a23); fma2(acc[3], w, b23);
        w = __half22float2(*(const __half2*)&wc.z);
        fma2(acc[4], w, a23); fma2(acc[5], w, b23);
        w = __half22float2(*(const __half2*)&wc.w);
        fma2(acc[6], w, a23); fma2(acc[7], w, b23);
    }
}

// ---- smem layout (byte offsets; all multiples of 16) ----
#define SB_W1   0                            // 3*L1_MAT halves = 123648 B
#define SB_W2   (SB_W1 + 3*L1_MAT*2)         // 123648; 3*L2_MAT halves = 24576 B
#define SB_B    (SB_W2 + 3*L2_MAT*2)         // 148224; 780 floats
#define SB_Z0   (SB_B + TOT_B*4)             // 151344
#define SB_Z1   (SB_Z0 + 2*CP0*4)            // 153456
#define SB_Z2   (SB_Z1 + 2*CP1*4)            // 155248
#define SB_ACT  (SB_Z2 + 2*CP2*4)            // 156272
#define SB_TOT  (SB_ACT + 3*5*2*UP0*4)       // 156272+16320 = 172592 B

#define KS0 5
#define KS1 7
#define KS2 16

__global__ __launch_bounds__(512, 1)
void lnn_main(const float* __restrict__ x, float* __restrict__ out)
{
    extern __shared__ __align__(16) char smraw[];
    __half* sW1 = (__half*)(smraw + SB_W1);
    __half* sW2 = (__half*)(smraw + SB_W2);
    float*  sb  = (float*)(smraw + SB_B);
    float*  z0  = (float*)(smraw + SB_Z0);
    float*  z1  = (float*)(smraw + SB_Z1);
    float*  z2  = (float*)(smraw + SB_Z2);
    float*  act = (float*)(smraw + SB_ACT);
    const uint4* sW1v = (const uint4*)sW1;
    const uint4* sW2v = (const uint4*)sW2;
    const uint4* gw0  = (const uint4*)g_wh + OFF_W0 / 8;
    float4* z0v = (float4*)z0;
    const float4* z1v = (const float4*)z1;
    const float4* z2v = (const float4*)z2;

    const int tid = threadIdx.x;

    // Fill smem caches
    {
        const uint4* gsrc = (const uint4*)g_wh;
        uint4* d1 = (uint4*)sW1;
        uint4* d2 = (uint4*)sW2;
        for (int i = tid; i < 3 * L1_MAT / 8; i += 512) d1[i] = gsrc[OFF_W1 / 8 + i];
        for (int i = tid; i < 3 * L2_MAT / 8; i += 512) d2[i] = gsrc[OFF_W2 / 8 + i];
    }
    for (int i = tid; i < TOT_B; i += 512) sb[i] = g_b[i];
    for (int i = tid; i < 2 * CP0; i += 512) z0[i] = 0.f;
    for (int i = tid; i < 2 * CP1; i += 512) z1[i] = 0.f;
    for (int i = tid; i < 2 * CP2; i += 512) z2[i] = 0.f;
    __syncthreads();

    const int b0 = blockIdx.x * 2;
    const float4* xv = (const float4*)x + (size_t)b0 * 1024 * 32;
    const int xr = tid >> 5, xi = tid & 31;   // for tid < 64

    float4 xreg = make_float4(0.f, 0.f, 0.f, 0.f);
    if (tid < 64) xreg = xv[((size_t)xr * 1024 + 0) * 32 + xi];

    for (int t = 0; t < 1024; ++t) {
        if (tid < 64) z0v[xr * (CP0 / 4) + xi] = xreg;
        __syncthreads();
        if (tid < 64) {
            int tn = (t + 1 < 1024) ? t + 1 : t;
            xreg = xv[((size_t)xr * 1024 + tn) * 32 + xi];
        }

        // ======== Cell 0 (streamed fp16): 3 mats x 34 ublk x 5 ks = 510 tasks
        if (tid < 510) {
            int ub = tid % 34, q = tid / 34;
            int ks = q % KS0, mat = q / KS0;
            int u0 = 4 * ub;
            float2 acc[8];
#pragma unroll
            for (int u = 0; u < 4; ++u) {
                float bv = (ks == 0) ? sb[OFF_B0 + mat * UP0 + u0 + u] : 0.f;
                acc[2 * u]     = make_float2(bv, 0.f);
                acc[2 * u + 1] = make_float2(bv, 0.f);
            }
            int kb = (ks * 66) / KS0, ke = ((ks + 1) * 66) / KS0;
            dot2<UP0>(gw0 + mat * (L0_MAT / 8), z0v, z0v + CP0 / 4, ub, kb, ke, acc);
            float* ap = act + ((mat * KS0 + ks) * 2) * UP0 + u0;
            *(float4*)ap         = make_float4(acc[0].x + acc[0].y, acc[2].x + acc[2].y,
                                               acc[4].x + acc[4].y, acc[6].x + acc[6].y);
            *(float4*)(ap + UP0) = make_float4(acc[1].x + acc[1].y, acc[3].x + acc[3].y,
                                               acc[5].x + acc[5].y, acc[7].x + acc[7].y);
        }
        __syncthreads();
        for (int u = tid; u < U0; u += 512) {
#pragma unroll
            for (int r = 0; r < 2; ++r) {
                float f1 = 0.f, f2 = 0.f, tt = 0.f;
#pragma unroll
                for (int ks = 0; ks < KS0; ++ks) {
                    f1 += act[((0 * KS0 + ks) * 2 + r) * UP0 + u];
                    f2 += act[((1 * KS0 + ks) * 2 + r) * UP0 + u];
                    tt += act[((2 * KS0 + ks) * 2 + r) * UP0 + u];
                }
                f1 = tanhf(f1); f2 = tanhf(f2);
                float s = 1.f / (1.f + expf(-tt));
                float h = f1 + s * (f2 - f1);
                z0[r * CP0 + F0 + u] = h;
                z1[r * CP1 + u]      = h;
            }
        }
        __syncthreads();

        // ======== Cell 1 (smem fp16): 3 mats x 23 ublk x 7 ks = 483 tasks
        if (tid < 483) {
            int ub = tid % 23, q = tid / 23;
            int ks = q % KS1, mat = q / KS1;
            int u0 = 4 * ub;
            float2 acc[8];
#pragma unroll
            for (int u = 0; u < 4; ++u) {
                float bv = (ks == 0) ? sb[OFF_B1 + mat * UP1 + u0 + u] : 0.f;
                acc[2 * u]     = make_float2(bv, 0.f);
                acc[2 * u + 1] = make_float2(bv, 0.f);
            }
            int kb = ks * 8, ke = kb + 8;
            dot2<UP1>(sW1v + mat * (L1_MAT / 8), z1v, z1v + CP1 / 4, ub, kb, ke, acc);
            float* ap = act + ((mat * KS1 + ks) * 2) * UP1 + u0;
            *(float4*)ap         = make_float4(acc[0].x + acc[0].y, acc[2].x + acc[2].y,
                                               acc[4].x + acc[4].y, acc[6].x + acc[6].y);
            *(float4*)(ap + UP1) = make_float4(acc[1].x + acc[1].y, acc[3].x + acc[3].y,
                                               acc[5].x + acc[5].y, acc[7].x + acc[7].y);
        }
        __syncthreads();
        for (int u = tid; u < U1; u += 512) {
#pragma unroll
            for (int r = 0; r < 2; ++r) {
                float f1 = 0.f, f2 = 0.f, tt = 0.f;
#pragma unroll
                for (int ks = 0; ks < KS1; ++ks) {
                    f1 += act[((0 * KS1 + ks) * 2 + r) * UP1 + u];
                    f2 += act[((1 * KS1 + ks) * 2 + r) * UP1 + u];
                    tt += act[((2 * KS1 + ks) * 2 + r) * UP1 + u];
                }
                f1 = tanhf(f1); f2 = tanhf(f2);
                float s = 1.f / (1.f + expf(-tt));
                float h = f1 + s * (f2 - f1);
                z1[r * CP1 + F1 + u] = h;
                z2[r * CP2 + u]      = h;
            }
        }
        __syncthreads();

        // ======== Cell 2 (smem fp16): 3 mats x 8 ublk x 16 ks = 384 tasks
        if (tid < 384) {
            int ub = tid & 7, q = tid >> 3;
            int ks = q & 15, mat = q >> 4;
            int u0 = 4 * ub;
            float2 acc[8];
#pragma unroll
            for (int u = 0; u < 4; ++u) {
                float bv = (ks == 0) ? sb[OFF_B2 + mat * UP2 + u0 + u] : 0.f;
                acc[2 * u]     = make_float2(bv, 0.f);
                acc[2 * u + 1] = make_float2(bv, 0.f);
            }
            int kb = ks * 2, ke = kb + 2;
            dot2<UP2>(sW2v + mat * (L2_MAT / 8), z2v, z2v + CP2 / 4, ub, kb, ke, acc);
            float* ap = act + ((mat * KS2 + ks) * 2) * UP2 + u0;
            *(float4*)ap         = make_float4(acc[0].x + acc[0].y, acc[2].x + acc[2].y,
                                               acc[4].x + acc[4].y, acc[6].x + acc[6].y);
            *(float4*)(ap + UP2) = make_float4(acc[1].x + acc[1].y, acc[3].x + acc[3].y,
                                               acc[5].x + acc[5].y, acc[7].x + acc[7].y);
        }
        __syncthreads();
        if (tid < U2) {
            int u = tid;
#pragma unroll
            for (int r = 0; r < 2; ++r) {
                float f1 = 0.f, f2 = 0.f, tt = 0.f;
#pragma unroll
                for (int ks = 0; ks < KS2; ++ks) {
                    f1 += act[((0 * KS2 + ks) * 2 + r) * UP2 + u];
                    f2 += act[((1 * KS2 + ks) * 2 + r) * UP2 + u];
                    tt += act[((2 * KS2 + ks) * 2 + r) * UP2 + u];
                }
                f1 = tanhf(f1); f2 = tanhf(f2);
                float s = 1.f / (1.f + expf(-tt));
                float h = f1 + s * (f2 - f1);
                z2[r * CP2 + F2 + u] = h;
                out[(((size_t)(b0 + r)) * 1024 + t) * 32 + u] = h;
            }
        }
        __syncthreads();
    }
}

// ---- fc head applied in place over out[256*1024][32] ----
__global__ __launch_bounds__(256)
void fc_kernel(float* __restrict__ out, const float* __restrict__ fcw,
               const float* __restrict__ fcb)
{
    __shared__ float w[1024];
    __shared__ float b[32];
    int tid = threadIdx.x;
    for (int i = tid; i < 1024; i += 256) w[i] = fcw[i];
    if (tid < 32) b[tid] = fcb[tid];
    __syncthreads();

    size_t pos = (size_t)blockIdx.x * 256 + tid;   // 262144 positions
    float4* p = reinterpret_cast<float4*>(out) + pos * 8;
    float h[32];
    float4 v[8];
#pragma unroll
    for (int i = 0; i < 8; ++i) v[i] = p[i];
#pragma unroll
    for (int i = 0; i < 8; ++i) {
        h[4 * i + 0] = v[i].x; h[4 * i + 1] = v[i].y;
        h[4 * i + 2] = v[i].z; h[4 * i + 3] = v[i].w;
    }
#pragma unroll
    for (int i = 0; i < 8; ++i) {
        float y[4];
#pragma unroll
        for (int j = 0; j < 4; ++j) {
            int o = 4 * i + j;
            float acc = b[o];
#pragma unroll
            for (int u = 0; u < 32; ++u) acc = fmaf(w[o * 32 + u], h[u], acc);
            y[j] = acc;
        }
        p[i] = make_float4(y[0], y[1], y[2], y[3]);
    }
}

// ============================================================================
extern "C" void kernel_launch(void* const* d_in, const int* in_sizes, int n_in,
                              void* d_out, int out_size)
{
    (void)n_in; (void)out_size;
    int base[3], mi[3], fwi, fbi;
    if (in_sizes[9] == U0 * C0) {          // interleaved dict order
        base[0] = 1;  mi[0] = 9;
        base[1] = 10; mi[1] = 18;
        base[2] = 19; mi[2] = 27;
        fwi = 28; fbi = 29;
    } else {                                // signature order
        base[0] = 1; base[1] = 9; base[2] = 17;
        fwi = 25; fbi = 26;
        mi[0] = 27; mi[1] = 28; mi[2] = 29;
    }

    const float* xin = (const float*)d_in[0];
    const float* fcw = (const float*)d_in[fwi];
    const float* fcb = (const float*)d_in[fbi];

#define LPTRS(l) \
    (const float*)d_in[base[l]+0], (const float*)d_in[base[l]+1], \
    (const float*)d_in[base[l]+2], (const float*)d_in[base[l]+3], \
    (const float*)d_in[base[l]+4], (const float*)d_in[base[l]+5], \
    (const float*)d_in[base[l]+6], (const float*)d_in[base[l]+7], \
    (const int*)d_in[mi[l]]

    pack_kernel<C0, CP0, U0, UP0><<<(3 * L0_MAT + 255) / 256, 256>>>(OFF_W0, OFF_B0, LPTRS(0));
    pack_kernel<C1, CP1, U1, UP1><<<(3 * L1_MAT + 255) / 256, 256>>>(OFF_W1, OFF_B1, LPTRS(1));
    pack_kernel<C2, CP2, U2, UP2><<<(3 * L2_MAT + 255) / 256, 256>>>(OFF_W2, OFF_B2, LPTRS(2));
#undef LPTRS

    static_assert(SB_TOT <= 232448, "smem over budget");
    cudaFuncSetAttribute(lnn_main, cudaFuncAttributeMaxDynamicSharedMemorySize,
                         SB_TOT);
    lnn_main<<<128, 512, SB_TOT>>>(xin, (float*)d_out);
    fc_kernel<<<1024, 256>>>((float*)d_out, fcw, fcb);
}

// round 12
// speedup vs baseline: 3.0795x; 1.0669x over previous
#include <cuda_runtime.h>
#include <cuda_fp16.h>

// ============================================================================
// CfC Liquid Neural Network, B=256, T=1024. Round 11.
//  - fp16 weights (fp32 z / fp32 acc) packed half2 (k,k+1) [k2][u]; FFMA2.
//  - 128 CTAs x 512 threads, 2 batch rows per CTA, 1024-step recurrence.
//  - cell1+cell2 weights smem-resident; cell0 streamed from L2 (KS0=5).
//  - NEW: fast __expf-based tanh/sigmoid; x-store fused into epi0 phase
//    (6 barriers/step instead of 7); epilogues widened to (u,row) threads.
//  - fc head applied by a separate elementwise kernel.
// ============================================================================

#define F0 128
#define U0 135
#define C0 263
#define CP0 264
#define UP0 136
#define F1 135
#define U1 89
#define C1 224
#define CP1 224
#define UP1 92
#define F2 89
#define U2 32
#define C2 121
#define CP2 128
#define UP2 32

#define L0_MAT (CP0*UP0)            // 35904 halves per mat
#define L1_MAT (CP1*UP1)            // 20608
#define L2_MAT (CP2*UP2)            // 4096
#define OFF_W0 0
#define OFF_W1 (3*L0_MAT)
#define OFF_W2 (OFF_W1 + 3*L1_MAT)
#define TOT_W  (OFF_W2 + 3*L2_MAT)

#define OFF_B0 0
#define OFF_B1 (3*UP0)
#define OFF_B2 (OFF_B1 + 3*UP1)
#define TOT_B  (OFF_B2 + 3*UP2)

__device__ __align__(16) __half g_wh[TOT_W];
__device__ float g_b[TOT_B];

// ---- packed fp32x2 FMA: d = a*b + d ----
__device__ __forceinline__ void fma2(float2& d, const float2& a, const float2& b)
{
    unsigned long long& dv = reinterpret_cast<unsigned long long&>(d);
    asm("fma.rn.f32x2 %0, %1, %2, %0;"
        : "+l"(dv)
        : "l"(reinterpret_cast<const unsigned long long&>(a)),
          "l"(reinterpret_cast<const unsigned long long&>(b)));
}

// ---- fast activations (MUFU-based; saturate correctly at +-inf) ----
__device__ __forceinline__ float fast_tanh(float x)
{
    float e = __expf(2.f * x);
    return 1.f - __fdividef(2.f, e + 1.f);
}
__device__ __forceinline__ float fast_sigmoid(float x)
{
    return __fdividef(1.f, 1.f + __expf(-x));
}

// ---- Pack: half linear idx within mat = (k2*UP + u)*2 + r, k = 2*k2 + r ----
template<int C, int CP, int U, int UP>
__global__ void pack_kernel(int woff, int boff,
    const float* __restrict__ ff1w, const float* __restrict__ ff1b,
    const float* __restrict__ ff2w, const float* __restrict__ ff2b,
    const float* __restrict__ taw,  const float* __restrict__ tab,
    const float* __restrict__ tbw,  const float* __restrict__ tbb,
    const int*   __restrict__ mask)
{
    const int per = CP * UP;
    const int n = 3 * per;
    for (int idx = blockIdx.x * blockDim.x + threadIdx.x; idx < n;
         idx += gridDim.x * blockDim.x) {
        int mat = idx / per;
        int e = idx - mat * per;
        int r = e & 1;
        int t1 = e >> 1;
        int u = t1 % UP;
        int k2 = t1 / UP;
        int c = 2 * k2 + r;
        float v = 0.f;
        if (c < C && u < U) {
            int src = u * C + c;
            if (mat == 0)      v = ff1w[src] * (float)mask[src];
            else if (mat == 1) v = ff2w[src] * (float)mask[src];
            else               v = taw[src] + tbw[src];
        }
        g_wh[woff + idx] = __float2half_rn(v);
    }
    for (int idx = blockIdx.x * blockDim.x + threadIdx.x; idx < 3 * UP;
         idx += gridDim.x * blockDim.x) {
        int mat = idx / UP;
        int u = idx - mat * UP;
        float v = 0.f;
        if (u < U) v = (mat == 0) ? ff1b[u] : (mat == 1 ? ff2b[u] : (tab[u] + tbb[u]));
        g_b[boff + idx] = v;
    }
}

// ---- Dot task: 4 units x 2 rows over k4 range [kb, ke); float2 acc over k ----
template<int UP>
__device__ __forceinline__ void dot2(
    const uint4* __restrict__ wbase,
    const float4* __restrict__ za, const float4* __restrict__ zb,
    int ub, int kb, int ke, float2 acc[8])
{
    const uint4* wp = wbase + (size_t)(2 * kb) * (UP / 4) + ub;
#pragma unroll 4
    for (int k4 = kb; k4 < ke; ++k4) {
        uint4 wa = wp[0];
        uint4 wc = wp[UP / 4];
        wp += UP / 2;
        float4 va = za[k4];
        float4 vb = zb[k4];
        float2 a01 = make_float2(va.x, va.y), a23 = make_float2(va.z, va.w);
        float2 b01 = make_float2(vb.x, vb.y), b23 = make_float2(vb.z, vb.w);
        float2 w;
        w = __half22float2(*(const __half2*)&wa.x);
        fma2(acc[0], w, a01); fma2(acc[1], w, b01);
        w = __half22float2(*(const __half2*)&wa.y);
        fma2(acc[2], w, a01); fma2(acc[3], w, b01);
        w = __half22float2(*(const __half2*)&wa.z);
        fma2(acc[4], w, a01); fma2(acc[5], w, b01);
        w = __half22float2(*(const __half2*)&wa.w);
        fma2(acc[6], w, a01); fma2(acc[7], w, b01);
        w = __half22float2(*(const __half2*)&wc.x);
        fma2(acc[0], w, a23); fma2(acc[1], w, b23);
        w = __half22float2(*(const __half2*)&wc.y);
        fma2(acc[2], w, a23); fma2(acc[3], w, b23);
        w = __half22float2(*(const __half2*)&wc.z);
        fma2(acc[4], w, a23); fma2(acc[5], w, b23);
        w = __half22float2(*(const __half2*)&wc.w);
        fma2(acc[6], w, a23); fma2(acc[7], w, b23);
    }
}

// ---- smem layout (byte offsets; all multiples of 16) ----
#define SB_W1   0                            // 3*L1_MAT halves
#define SB_W2   (SB_W1 + 3*L1_MAT*2)
#define SB_B    (SB_W2 + 3*L2_MAT*2)
#define SB_Z0   (SB_B + TOT_B*4)
#define SB_Z1   (SB_Z0 + 2*CP0*4)
#define SB_Z2   (SB_Z1 + 2*CP1*4)
#define SB_ACT  (SB_Z2 + 2*CP2*4)
#define SB_TOT  (SB_ACT + 3*5*2*UP0*4)       // 172592 B

#define KS0 5
#define KS1 7
#define KS2 16

__global__ __launch_bounds__(512, 1)
void lnn_main(const float* __restrict__ x, float* __restrict__ out)
{
    extern __shared__ __align__(16) char smraw[];
    __half* sW1 = (__half*)(smraw + SB_W1);
    __half* sW2 = (__half*)(smraw + SB_W2);
    float*  sb  = (float*)(smraw + SB_B);
    float*  z0  = (float*)(smraw + SB_Z0);
    float*  z1  = (float*)(smraw + SB_Z1);
    float*  z2  = (float*)(smraw + SB_Z2);
    float*  act = (float*)(smraw + SB_ACT);
    const uint4* sW1v = (const uint4*)sW1;
    const uint4* sW2v = (const uint4*)sW2;
    const uint4* gw0  = (const uint4*)g_wh + OFF_W0 / 8;
    float4* z0v = (float4*)z0;
    const float4* z1v = (const float4*)z1;
    const float4* z2v = (const float4*)z2;

    const int tid = threadIdx.x;

    // Fill smem caches
    {
        const uint4* gsrc = (const uint4*)g_wh;
        uint4* d1 = (uint4*)sW1;
        uint4* d2 = (uint4*)sW2;
        for (int i = tid; i < 3 * L1_MAT / 8; i += 512) d1[i] = gsrc[OFF_W1 / 8 + i];
        for (int i = tid; i < 3 * L2_MAT / 8; i += 512) d2[i] = gsrc[OFF_W2 / 8 + i];
    }
    for (int i = tid; i < TOT_B; i += 512) sb[i] = g_b[i];
    for (int i = tid; i < 2 * CP0; i += 512) z0[i] = 0.f;
    for (int i = tid; i < 2 * CP1; i += 512) z1[i] = 0.f;
    for (int i = tid; i < 2 * CP2; i += 512) z2[i] = 0.f;
    __syncthreads();

    const int b0 = blockIdx.x * 2;
    const float4* xv = (const float4*)x + (size_t)b0 * 1024 * 32;
    // x-prefetch threads: 448..511 (disjoint from epi0's 0..269)
    const int xr = (tid - 448) >> 5, xi = (tid - 448) & 31;

    float4 xreg = make_float4(0.f, 0.f, 0.f, 0.f);
    if (tid >= 448) {
        // store x_0 directly; prefetch x_1
        z0v[xr * (CP0 / 4) + xi] = xv[((size_t)xr * 1024 + 0) * 32 + xi];
    }
    __syncthreads();
    if (tid >= 448) xreg = xv[((size_t)xr * 1024 + 1) * 32 + xi];

    for (int t = 0; t < 1024; ++t) {
        // ======== Cell 0 (streamed fp16): 3 mats x 34 ublk x 5 ks = 510 tasks
        if (tid < 510) {
            int ub = tid % 34, q = tid / 34;
            int ks = q % KS0, mat = q / KS0;
            int u0 = 4 * ub;
            float2 acc[8];
#pragma unroll
            for (int u = 0; u < 4; ++u) {
                float bv = (ks == 0) ? sb[OFF_B0 + mat * UP0 + u0 + u] : 0.f;
                acc[2 * u]     = make_float2(bv, 0.f);
                acc[2 * u + 1] = make_float2(bv, 0.f);
            }
            int kb = (ks * 66) / KS0, ke = ((ks + 1) * 66) / KS0;
            dot2<UP0>(gw0 + mat * (L0_MAT / 8), z0v, z0v + CP0 / 4, ub, kb, ke, acc);
            float* ap = act + ((mat * KS0 + ks) * 2) * UP0 + u0;
            *(float4*)ap         = make_float4(acc[0].x + acc[0].y, acc[2].x + acc[2].y,
                                               acc[4].x + acc[4].y, acc[6].x + acc[6].y);
            *(float4*)(ap + UP0) = make_float4(acc[1].x + acc[1].y, acc[3].x + acc[3].y,
                                               acc[5].x + acc[5].y, acc[7].x + acc[7].y);
        }
        __syncthreads();

        // ======== epi0 (270 thr) fused with x_{t+1} store (threads 448+)
        if (tid < 270) {
            int u = tid >> 1, r = tid & 1;
            float f1 = 0.f, f2 = 0.f, tt = 0.f;
#pragma unroll
            for (int ks = 0; ks < KS0; ++ks) {
                f1 += act[((0 * KS0 + ks) * 2 + r) * UP0 + u];
                f2 += act[((1 * KS0 + ks) * 2 + r) * UP0 + u];
                tt += act[((2 * KS0 + ks) * 2 + r) * UP0 + u];
            }
            f1 = fast_tanh(f1); f2 = fast_tanh(f2);
            float s = fast_sigmoid(tt);
            float h = f1 + s * (f2 - f1);
            z0[r * CP0 + F0 + u] = h;
            z1[r * CP1 + u]      = h;
        } else if (tid >= 448) {
            z0v[xr * (CP0 / 4) + xi] = xreg;   // x_{t+1} into z0 (x-slice dead)
        }
        __syncthreads();
        if (tid >= 448) {
            int tn = (t + 2 < 1024) ? t + 2 : 1023;
            xreg = xv[((size_t)xr * 1024 + tn) * 32 + xi];
        }

        // ======== Cell 1 (smem fp16): 3 mats x 23 ublk x 7 ks = 483 tasks
        if (tid < 483) {
            int ub = tid % 23, q = tid / 23;
            int ks = q % KS1, mat = q / KS1;
            int u0 = 4 * ub;
            float2 acc[8];
#pragma unroll
            for (int u = 0; u < 4; ++u) {
                float bv = (ks == 0) ? sb[OFF_B1 + mat * UP1 + u0 + u] : 0.f;
                acc[2 * u]     = make_float2(bv, 0.f);
                acc[2 * u + 1] = make_float2(bv, 0.f);
            }
            int kb = ks * 8, ke = kb + 8;
            dot2<UP1>(sW1v + mat * (L1_MAT / 8), z1v, z1v + CP1 / 4, ub, kb, ke, acc);
            float* ap = act + ((mat * KS1 + ks) * 2) * UP1 + u0;
            *(float4*)ap         = make_float4(acc[0].x + acc[0].y, acc[2].x + acc[2].y,
                                               acc[4].x + acc[4].y, acc[6].x + acc[6].y);
            *(float4*)(ap + UP1) = make_float4(acc[1].x + acc[1].y, acc[3].x + acc[3].y,
                                               acc[5].x + acc[5].y, acc[7].x + acc[7].y);
        }
        __syncthreads();
        if (tid < 178) {
            int u = tid >> 1, r = tid & 1;
            float f1 = 0.f, f2 = 0.f, tt = 0.f;
#pragma unroll
            for (int ks = 0; ks < KS1; ++ks) {
                f1 += act[((0 * KS1 + ks) * 2 + r) * UP1 + u];
                f2 += act[((1 * KS1 + ks) * 2 + r) * UP1 + u];
                tt += act[((2 * KS1 + ks) * 2 + r) * UP1 + u];
            }
            f1 = fast_tanh(f1); f2 = fast_tanh(f2);
            float s = fast_sigmoid(tt);
            float h = f1 + s * (f2 - f1);
            z1[r * CP1 + F1 + u] = h;
            z2[r * CP2 + u]      = h;
        }
        __syncthreads();

        // ======== Cell 2 (smem fp16): 3 mats x 8 ublk x 16 ks = 384 tasks
        if (tid < 384) {
            int ub = tid & 7, q = tid >> 3;
            int ks = q & 15, mat = q >> 4;
            int u0 = 4 * ub;
            float2 acc[8];
#pragma unroll
            for (int u = 0; u < 4; ++u) {
                float bv = (ks == 0) ? sb[OFF_B2 + mat * UP2 + u0 + u] : 0.f;
                acc[2 * u]     = make_float2(bv, 0.f);
                acc[2 * u + 1] = make_float2(bv, 0.f);
            }
            int kb = ks * 2, ke = kb + 2;
            dot2<UP2>(sW2v + mat * (L2_MAT / 8), z2v, z2v + CP2 / 4, ub, kb, ke, acc);
            float* ap = act + ((mat * KS2 + ks) * 2) * UP2 + u0;
            *(float4*)ap         = make_float4(acc[0].x + acc[0].y, acc[2].x + acc[2].y,
                                               acc[4].x + acc[4].y, acc[6].x + acc[6].y);
            *(float4*)(ap + UP2) = make_float4(acc[1].x + acc[1].y, acc[3].x + acc[3].y,
                                               acc[5].x + acc[5].y, acc[7].x + acc[7].y);
        }
        __syncthreads();
        if (tid < 64) {
            int u = tid >> 1, r = tid & 1;
            float f1 = 0.f, f2 = 0.f, tt = 0.f;
#pragma unroll
            for (int ks = 0; ks < KS2; ++ks) {
                f1 += act[((0 * KS2 + ks) * 2 + r) * UP2 + u];
                f2 += act[((1 * KS2 + ks) * 2 + r) * UP2 + u];
                tt += act[((2 * KS2 + ks) * 2 + r) * UP2 + u];
            }
            f1 = fast_tanh(f1); f2 = fast_tanh(f2);
            float s = fast_sigmoid(tt);
            float h = f1 + s * (f2 - f1);
            z2[r * CP2 + F2 + u] = h;
            out[(((size_t)(b0 + r)) * 1024 + t) * 32 + u] = h;
        }
        __syncthreads();
    }
}

// ---- fc head applied in place over out[256*1024][32] ----
__global__ __launch_bounds__(256)
void fc_kernel(float* __restrict__ out, const float* __restrict__ fcw,
               const float* __restrict__ fcb)
{
    __shared__ float w[1024];
    __shared__ float b[32];
    int tid = threadIdx.x;
    for (int i = tid; i < 1024; i += 256) w[i] = fcw[i];
    if (tid < 32) b[tid] = fcb[tid];
    __syncthreads();

    size_t pos = (size_t)blockIdx.x * 256 + tid;
    float4* p = reinterpret_cast<float4*>(out) + pos * 8;
    float h[32];
    float4 v[8];
#pragma unroll
    for (int i = 0; i < 8; ++i) v[i] = p[i];
#pragma unroll
    for (int i = 0; i < 8; ++i) {
        h[4 * i + 0] = v[i].x; h[4 * i + 1] = v[i].y;
        h[4 * i + 2] = v[i].z; h[4 * i + 3] = v[i].w;
    }
#pragma unroll
    for (int i = 0; i < 8; ++i) {
        float y[4];
#pragma unroll
        for (int j = 0; j < 4; ++j) {
            int o = 4 * i + j;
            float acc = b[o];
#pragma unroll
            for (int u = 0; u < 32; ++u) acc = fmaf(w[o * 32 + u], h[u], acc);
            y[j] = acc;
        }
        p[i] = make_float4(y[0], y[1], y[2], y[3]);
    }
}

// ============================================================================
extern "C" void kernel_launch(void* const* d_in, const int* in_sizes, int n_in,
                              void* d_out, int out_size)
{
    (void)n_in; (void)out_size;
    int base[3], mi[3], fwi, fbi;
    if (in_sizes[9] == U0 * C0) {          // interleaved dict order
        base[0] = 1;  mi[0] = 9;
        base[1] = 10; mi[1] = 18;
        base[2] = 19; mi[2] = 27;
        fwi = 28; fbi = 29;
    } else {                                // signature order
        base[0] = 1; base[1] = 9; base[2] = 17;
        fwi = 25; fbi = 26;
        mi[0] = 27; mi[1] = 28; mi[2] = 29;
    }

    const float* xin = (const float*)d_in[0];
    const float* fcw = (const float*)d_in[fwi];
    const float* fcb = (const float*)d_in[fbi];

#define LPTRS(l) \
    (const float*)d_in[base[l]+0], (const float*)d_in[base[l]+1], \
    (const float*)d_in[base[l]+2], (const float*)d_in[base[l]+3], \
    (const float*)d_in[base[l]+4], (const float*)d_in[base[l]+5], \
    (const float*)d_in[base[l]+6], (const float*)d_in[base[l]+7], \
    (const int*)d_in[mi[l]]

    pack_kernel<C0, CP0, U0, UP0><<<(3 * L0_MAT + 255) / 256, 256>>>(OFF_W0, OFF_B0, LPTRS(0));
    pack_kernel<C1, CP1, U1, UP1><<<(3 * L1_MAT + 255) / 256, 256>>>(OFF_W1, OFF_B1, LPTRS(1));
    pack_kernel<C2, CP2, U2, UP2><<<(3 * L2_MAT + 255) / 256, 256>>>(OFF_W2, OFF_B2, LPTRS(2));
#undef LPTRS

    static_assert(SB_TOT <= 232448, "smem over budget");
    cudaFuncSetAttribute(lnn_main, cudaFuncAttributeMaxDynamicSharedMemorySize,
                         SB_TOT);
    lnn_main<<<128, 512, SB_TOT>>>(xin, (float*)d_out);
    fc_kernel<<<1024, 256>>>((float*)d_out, fcw, fcb);
}